// round 12
// baseline (speedup 1.0000x reference)
#include <cuda_runtime.h>
#include <cuda_bf16.h>
#include <math.h>
#include <cstdint>

// ---------------------------------------------------------------------------
// Problem constants
// ---------------------------------------------------------------------------
#define BATCH   4
#define SEQ     1024
#define DIM     1024
#define NH      16
#define HD      64
#define MLP     4096
#define ROWS    (BATCH*SEQ)       // 4096
#define QKVN    (5*NH*HD)         // 5120
#define EPSV    1e-6f
#define ATTN_CLIP 100.0f
#define NORM_CLIP 1000.0f

// ---------------------------------------------------------------------------
// PTX helpers — ONLY plain-sm_103-legal features: cp.async, ldmatrix, mma.sync
// ---------------------------------------------------------------------------
__device__ __forceinline__ uint32_t smem_to_u32(const void* p) {
    uint32_t a;
    asm("{ .reg .u64 t; cvta.to.shared.u64 t, %1; cvt.u32.u64 %0, t; }" : "=r"(a) : "l"(p));
    return a;
}
#define CP_ASYNC16(dst, src) \
    asm volatile("cp.async.cg.shared.global [%0], [%1], 16;" :: "r"(dst), "l"(src) : "memory")
#define CP_COMMIT() asm volatile("cp.async.commit_group;" ::: "memory")
#define CP_WAIT1()  asm volatile("cp.async.wait_group 1;" ::: "memory")

__device__ __forceinline__ void ldsm4(uint32_t& r0, uint32_t& r1, uint32_t& r2, uint32_t& r3,
                                      uint32_t addr) {
    asm volatile("ldmatrix.sync.aligned.m8n8.x4.shared.b16 {%0,%1,%2,%3}, [%4];"
                 : "=r"(r0), "=r"(r1), "=r"(r2), "=r"(r3) : "r"(addr));
}
__device__ __forceinline__ void ldsm4t(uint32_t& r0, uint32_t& r1, uint32_t& r2, uint32_t& r3,
                                       uint32_t addr) {
    asm volatile("ldmatrix.sync.aligned.m8n8.x4.trans.shared.b16 {%0,%1,%2,%3}, [%4];"
                 : "=r"(r0), "=r"(r1), "=r"(r2), "=r"(r3) : "r"(addr));
}
__device__ __forceinline__ void mma16816(float& c0, float& c1, float& c2, float& c3,
                                         uint32_t a0, uint32_t a1, uint32_t a2, uint32_t a3,
                                         uint32_t b0, uint32_t b1) {
    asm volatile("mma.sync.aligned.m16n8k16.row.col.f32.bf16.bf16.f32 "
                 "{%0,%1,%2,%3}, {%4,%5,%6,%7}, {%8,%9}, {%0,%1,%2,%3};"
                 : "+f"(c0), "+f"(c1), "+f"(c2), "+f"(c3)
                 : "r"(a0), "r"(a1), "r"(a2), "r"(a3), "r"(b0), "r"(b1));
}

__device__ __forceinline__ void split2(float v, __nv_bfloat16& h, __nv_bfloat16& l) {
    h = __float2bfloat16(v);
    l = __float2bfloat16(v - __bfloat162float(h));
}
__device__ __forceinline__ uint32_t bf16bits(__nv_bfloat16 h) {
    unsigned short u; memcpy(&u, &h, 2); return (uint32_t)u;
}
__device__ __forceinline__ void packsplit(float a, float b, uint32_t& hi, uint32_t& lo) {
    __nv_bfloat16 ah, al, bh, bl;
    split2(a, ah, al); split2(b, bh, bl);
    hi = bf16bits(ah) | (bf16bits(bh) << 16);
    lo = bf16bits(al) | (bf16bits(bl) << 16);
}

// ---------------------------------------------------------------------------
// Scratch (static device globals)
// ---------------------------------------------------------------------------
__device__ __nv_bfloat16 g_h1h[ROWS*DIM],  g_h1l[ROWS*DIM];
__device__ __nv_bfloat16 g_qvh[ROWS*QKVN], g_qvl[ROWS*QKVN];
__device__ __nv_bfloat16 g_ath[ROWS*DIM],  g_atl[ROWS*DIM];
__device__ float         g_x2 [ROWS*DIM];
__device__ __nv_bfloat16 g_h2h[ROWS*DIM],  g_h2l[ROWS*DIM];
__device__ __nv_bfloat16 g_f1h[ROWS*MLP],  g_f1l[ROWS*MLP];
__device__ __nv_bfloat16 g_wqh[QKVN*DIM],  g_wql[QKVN*DIM];
__device__ __nv_bfloat16 g_wph[DIM*DIM],   g_wpl[DIM*DIM];
__device__ __nv_bfloat16 g_w1h[MLP*DIM],   g_w1l[MLP*DIM];
__device__ __nv_bfloat16 g_w2h[DIM*MLP],   g_w2l[DIM*MLP];
__device__ float g_part[BATCH*64];
__device__ float g_nx  [BATCH];
__device__ float g_lam;

// ---------------------------------------------------------------------------
// GRN reductions
// ---------------------------------------------------------------------------
__global__ void reduce_sq_kernel(const float* __restrict__ x)
{
    const int b   = blockIdx.y;
    const int tid = threadIdx.x;
    const float4* xb = (const float4*)(x + (size_t)b * (SEQ*DIM));
    const int n4 = SEQ*DIM/4;
    float s = 0.f;
    for (int i = blockIdx.x*blockDim.x + tid; i < n4; i += gridDim.x*blockDim.x) {
        float4 v = xb[i];
        s += v.x*v.x + v.y*v.y + v.z*v.z + v.w*v.w;
    }
    #pragma unroll
    for (int o = 16; o; o >>= 1) s += __shfl_xor_sync(0xffffffffu, s, o);
    __shared__ float ws[8];
    if ((tid & 31) == 0) ws[tid >> 5] = s;
    __syncthreads();
    if (tid < 8) {
        s = ws[tid];
        #pragma unroll
        for (int o = 4; o; o >>= 1) s += __shfl_xor_sync(0xffu, s, o);
        if (tid == 0) g_part[b*64 + blockIdx.x] = s;
    }
}

__global__ void grn_finalize_kernel()
{
    const int b = blockIdx.x, t = threadIdx.x;
    float s = g_part[b*64 + t] + g_part[b*64 + t + 32];
    #pragma unroll
    for (int o = 16; o; o >>= 1) s += __shfl_xor_sync(0xffffffffu, s, o);
    if (t == 0) {
        float ss = fminf(fmaxf(s, EPSV), NORM_CLIP);
        float gx = sqrtf(ss);
        float nx = gx / (gx + EPSV);
        nx = fminf(fmaxf(nx, -NORM_CLIP), NORM_CLIP);
        g_nx[b] = nx;
    }
}

__global__ void grn_apply_split_kernel(const float* __restrict__ x,
                                       const float* __restrict__ gamma,
                                       const float* __restrict__ beta,
                                       __nv_bfloat16* __restrict__ hi,
                                       __nv_bfloat16* __restrict__ lo)
{
    const int i  = blockIdx.x*blockDim.x + threadIdx.x;
    const int n4 = ROWS*DIM/4;
    if (i >= n4) return;
    const int d4 = i & (DIM/4 - 1);
    const int b  = i / (SEQ*DIM/4);
    const float nx = g_nx[b];
    float4 xv = ((const float4*)x)[i];
    float4 gv = ((const float4*)gamma)[d4];
    float4 bv = ((const float4*)beta)[d4];
    float r0 = gv.x*(xv.x*nx) + bv.x + xv.x;
    float r1 = gv.y*(xv.y*nx) + bv.y + xv.y;
    float r2 = gv.z*(xv.z*nx) + bv.z + xv.z;
    float r3 = gv.w*(xv.w*nx) + bv.w + xv.w;
    __align__(8) __nv_bfloat16 hb[4], lb[4];
    split2(r0, hb[0], lb[0]); split2(r1, hb[1], lb[1]);
    split2(r2, hb[2], lb[2]); split2(r3, hb[3], lb[3]);
    ((uint2*)hi)[i] = *(uint2*)hb;
    ((uint2*)lo)[i] = *(uint2*)lb;
}

// ---------------------------------------------------------------------------
// Weight transpose + bf16 split: w[K,N] -> hi/lo[N,K]
// ---------------------------------------------------------------------------
__global__ void wtrans_kernel(const float* __restrict__ w,
                              __nv_bfloat16* __restrict__ hi,
                              __nv_bfloat16* __restrict__ lo, int K, int N)
{
    __shared__ float t[32][33];
    const int n0 = blockIdx.x << 5, k0 = blockIdx.y << 5;
    const int tx = threadIdx.x, ty = threadIdx.y;
    #pragma unroll
    for (int i = ty; i < 32; i += 8)
        t[i][tx] = w[(size_t)(k0 + i)*N + n0 + tx];
    __syncthreads();
    #pragma unroll
    for (int i = ty; i < 32; i += 8) {
        float v = t[tx][i];
        __nv_bfloat16 h, l;
        split2(v, h, l);
        size_t o = (size_t)(n0 + i)*K + k0 + tx;
        hi[o] = h; lo[o] = l;
    }
}

// ---------------------------------------------------------------------------
// lambda scalar
// ---------------------------------------------------------------------------
__global__ void lam_kernel(const float* __restrict__ lq1, const float* __restrict__ lk1,
                           const float* __restrict__ lq2, const float* __restrict__ lk2)
{
    const int t = threadIdx.x;
    float a = lq1[t]*lk1[t] + lq1[t+32]*lk1[t+32];
    float c = lq2[t]*lk2[t] + lq2[t+32]*lk2[t+32];
    #pragma unroll
    for (int o = 16; o; o >>= 1) {
        a += __shfl_xor_sync(0xffffffffu, a, o);
        c += __shfl_xor_sync(0xffffffffu, c, o);
    }
    if (t == 0) {
        float l1 = fminf(fmaxf(a, -10.f), 10.f);
        float l2 = fminf(fmaxf(c, -10.f), 10.f);
        g_lam = fminf(fmaxf(expf(l1) - expf(l2) + 0.2f, 0.1f), 5.0f);
    }
}

// ---------------------------------------------------------------------------
// HMMA GEMM: C[M,N] = A[M,K] @ B[N,K]^T   fp32 via bf16 hi/lo split (3 passes)
// CTA 128x256, BK=32, 3-stage cp.async pipeline, 8 warps (2Mx4N) x 64x64 tile.
// ---------------------------------------------------------------------------
#define HG_MT 128
#define HG_NT 256
#define HG_BK 32
#define HG_AT 8192                    // A tile bytes (128*32*2)
#define HG_BT 16384                   // B tile bytes (256*32*2)
#define HG_STAGE (2*HG_AT + 2*HG_BT)  // 49152: Ah Al Bh Bl
#define HG_SMEM  (3*HG_STAGE)         // 147456

__device__ __forceinline__ void hg_load_tile(uint32_t sbase, int tid,
    const __nv_bfloat16* __restrict__ g, int rbase, int K, int kt, int iters)
{
    for (int it = 0; it < iters; it++) {
        int f   = tid + it*256;
        int row = f >> 2, c = f & 3;
        int sw  = c ^ ((row >> 1) & 3);
        uint32_t sa = sbase + (uint32_t)(row*64 + sw*16);
        CP_ASYNC16(sa, g + (size_t)(rbase + row)*K + kt + c*8);
    }
}

__device__ __forceinline__ void hg_load_stage(uint32_t sbase, int tid,
    const __nv_bfloat16* __restrict__ Ahi, const __nv_bfloat16* __restrict__ Alo,
    const __nv_bfloat16* __restrict__ Bhi, const __nv_bfloat16* __restrict__ Blo,
    int row0, int col0, int K, int kt)
{
    hg_load_tile(sbase,                 tid, Ahi, row0, K, kt, 2);
    hg_load_tile(sbase + HG_AT,         tid, Alo, row0, K, kt, 2);
    hg_load_tile(sbase + 2*HG_AT,         tid, Bhi, col0, K, kt, 4);
    hg_load_tile(sbase + 2*HG_AT + HG_BT, tid, Blo, col0, K, kt, 4);
}

template<int DO_BIAS, int DO_RES, int DO_SILU, int OUT_F32, int OUT_SPLIT>
__global__ __launch_bounds__(256, 1)
void hmma_gemm_kernel(
    const __nv_bfloat16* __restrict__ Ahi, const __nv_bfloat16* __restrict__ Alo,
    const __nv_bfloat16* __restrict__ Bhi, const __nv_bfloat16* __restrict__ Blo,
    const float* __restrict__ bias, const float* __restrict__ res,
    float* __restrict__ Cf, __nv_bfloat16* __restrict__ Chi, __nv_bfloat16* __restrict__ Clo,
    int M, int N, int K)
{
    extern __shared__ char smem[];
    const uint32_t sb = smem_to_u32(smem);
    const int tid  = threadIdx.x;
    const int wid  = tid >> 5;
    const int lane = tid & 31;
    const int wm   = (wid & 1) << 6;          // 0 or 64
    const int wn   = (wid >> 1) << 6;         // 0,64,128,192
    const int row0 = blockIdx.y * HG_MT;
    const int col0 = blockIdx.x * HG_NT;

    float acc[4][8][4];
    #pragma unroll
    for (int i = 0; i < 4; i++)
        #pragma unroll
        for (int j = 0; j < 8; j++)
            #pragma unroll
            for (int q = 0; q < 4; q++) acc[i][j][q] = 0.f;

    const int S = K / HG_BK;
    hg_load_stage(sb, tid, Ahi, Alo, Bhi, Blo, row0, col0, K, 0);
    CP_COMMIT();
    hg_load_stage(sb + HG_STAGE, tid, Ahi, Alo, Bhi, Blo, row0, col0, K, HG_BK);
    CP_COMMIT();

    const int lrow = lane & 15;
    const int lhi  = lane >> 4;

    int buf = 0;
    for (int i = 0; i < S; i++) {
        CP_WAIT1();
        __syncthreads();
        if (i + 2 < S)
            hg_load_stage(sb + ((buf + 2) % 3)*HG_STAGE, tid, Ahi, Alo, Bhi, Blo,
                          row0, col0, K, (i + 2)*HG_BK);
        CP_COMMIT();

        const uint32_t bA  = sb + buf*HG_STAGE;
        const uint32_t bAl = bA + HG_AT;
        const uint32_t bB  = bA + 2*HG_AT;
        const uint32_t bBl = bB + HG_BT;

        #pragma unroll
        for (int h = 0; h < 2; h++) {
            uint32_t ah[4][4], al[4][4];
            #pragma unroll
            for (int tm = 0; tm < 4; tm++) {
                int row = wm + tm*16 + lrow;
                int c   = h*2 + lhi;
                uint32_t off = (uint32_t)(row*64 + ((c ^ ((row >> 1) & 3))*16));
                ldsm4(ah[tm][0], ah[tm][1], ah[tm][2], ah[tm][3], bA  + off);
                ldsm4(al[tm][0], al[tm][1], al[tm][2], al[tm][3], bAl + off);
            }
            #pragma unroll
            for (int hn = 0; hn < 2; hn++) {      // two 32-col halves of the 64-col warp tile
                uint32_t bh[4][2], bl[4][2];
                #pragma unroll
                for (int u = 0; u < 2; u++) {
                    int row = wn + hn*32 + u*16 + lrow;
                    int c   = h*2 + lhi;
                    uint32_t off = (uint32_t)(row*64 + ((c ^ ((row >> 1) & 3))*16));
                    uint32_t r0, r1, r2, r3;
                    ldsm4(r0, r1, r2, r3, bB + off);
                    bh[2*u][0] = r0; bh[2*u][1] = r2; bh[2*u+1][0] = r1; bh[2*u+1][1] = r3;
                    ldsm4(r0, r1, r2, r3, bBl + off);
                    bl[2*u][0] = r0; bl[2*u][1] = r2; bl[2*u+1][0] = r1; bl[2*u+1][1] = r3;
                }
                #pragma unroll
                for (int tm = 0; tm < 4; tm++)
                    #pragma unroll
                    for (int tn = 0; tn < 4; tn++) {
                        float* a4 = acc[tm][hn*4 + tn];
                        mma16816(a4[0], a4[1], a4[2], a4[3],
                                 ah[tm][0], ah[tm][1], ah[tm][2], ah[tm][3], bh[tn][0], bh[tn][1]);
                        mma16816(a4[0], a4[1], a4[2], a4[3],
                                 ah[tm][0], ah[tm][1], ah[tm][2], ah[tm][3], bl[tn][0], bl[tn][1]);
                        mma16816(a4[0], a4[1], a4[2], a4[3],
                                 al[tm][0], al[tm][1], al[tm][2], al[tm][3], bh[tn][0], bh[tn][1]);
                    }
            }
        }
        buf = (buf + 1) % 3;
    }

    // epilogue: warp covers rows wm..wm+64, cols wn..wn+64
    #pragma unroll
    for (int tm = 0; tm < 4; tm++) {
        #pragma unroll
        for (int tn = 0; tn < 8; tn++) {
            const int gr0 = row0 + wm + tm*16 + (lane >> 2);
            const int gc  = col0 + wn + tn*8 + 2*(lane & 3);
            #pragma unroll
            for (int hh = 0; hh < 2; hh++) {
                const int gr = gr0 + hh*8;
                float v0 = acc[tm][tn][2*hh];
                float v1 = acc[tm][tn][2*hh + 1];
                if (DO_BIAS) { v0 += bias[gc]; v1 += bias[gc + 1]; }
                if (DO_SILU) {
                    v0 = v0 / (1.f + __expf(-v0));
                    v1 = v1 / (1.f + __expf(-v1));
                }
                if (DO_RES) {
                    float2 rv = *(const float2*)(res + (size_t)gr*N + gc);
                    v0 += rv.x; v1 += rv.y;
                }
                if (OUT_F32)
                    *(float2*)(Cf + (size_t)gr*N + gc) = make_float2(v0, v1);
                if (OUT_SPLIT) {
                    __align__(4) __nv_bfloat16 hp[2], lp[2];
                    split2(v0, hp[0], lp[0]); split2(v1, hp[1], lp[1]);
                    *(uint32_t*)(Chi + (size_t)gr*N + gc) = *(uint32_t*)hp;
                    *(uint32_t*)(Clo + (size_t)gr*N + gc) = *(uint32_t*)lp;
                }
            }
        }
    }
}

// ---------------------------------------------------------------------------
// HMMA differential flash-attention (unchanged from R8 passing kernel)
// ---------------------------------------------------------------------------
#define AT_BQ   128
#define AT_BK   64
#define AT_QT   (AT_BQ*128)
#define AT_KT   (AT_BK*128)
#define AT_SBASE (4*AT_QT)
#define AT_STAGE (6*AT_KT)
#define AT_SMEM  (AT_SBASE + 2*AT_STAGE)
#define ASW(row, c) ((uint32_t)((row)*128 + (((c) ^ ((row) & 7))*16)))

__device__ __forceinline__ void at_load_stage(uint32_t base, int tid,
    const __nv_bfloat16* __restrict__ qh, const __nv_bfloat16* __restrict__ ql,
    size_t krow0, int hof)
{
    #pragma unroll
    for (int i = 0; i < 12; i++) {
        int f = tid + i*256;
        int tile = f >> 9, rem = f & 511;
        int row = rem >> 3, c = rem & 7;
        const __nv_bfloat16* src = (tile & 1) ? ql : qh;
        int off = (tile < 4) ? (2 + (tile >> 1))*NH*HD : 4*NH*HD;
        CP_ASYNC16(base + tile*AT_KT + ASW(row, c),
                   src + (krow0 + row)*QKVN + hof + off + c*8);
    }
}

__global__ __launch_bounds__(256, 1) void diff_attn_mma_kernel(
    const __nv_bfloat16* __restrict__ qh, const __nv_bfloat16* __restrict__ ql,
    __nv_bfloat16* __restrict__ outh, __nv_bfloat16* __restrict__ outl)
{
    extern __shared__ char smem[];
    const uint32_t sb = smem_to_u32(smem);
    const int tid = threadIdx.x, wid = tid >> 5, lane = tid & 31;
    const int q0  = blockIdx.x * AT_BQ;
    const int hof = blockIdx.y * HD;
    const int b   = blockIdx.z;
    const size_t grow0 = (size_t)(b*SEQ + q0);
    const size_t kbase = (size_t)(b*SEQ);

    #pragma unroll
    for (int i = 0; i < 16; i++) {
        int f = tid + i*256;
        int tile = f >> 10, rem = f & 1023;
        int row = rem >> 3, c = rem & 7;
        const __nv_bfloat16* src = (tile & 1) ? ql : qh;
        int off = (tile >> 1) ? NH*HD : 0;
        CP_ASYNC16(sb + tile*AT_QT + ASW(row, c),
                   src + (grow0 + row)*QKVN + hof + off + c*8);
    }
    at_load_stage(sb + AT_SBASE, tid, qh, ql, kbase, hof);
    CP_COMMIT();
    at_load_stage(sb + AT_SBASE + AT_STAGE, tid, qh, ql, kbase + AT_BK, hof);
    CP_COMMIT();

    float O[2][8][4];
    float mr[2][2], lr[2][2];
    #pragma unroll
    for (int a = 0; a < 2; a++) {
        mr[a][0] = -1e30f; mr[a][1] = -1e30f; lr[a][0] = 0.f; lr[a][1] = 0.f;
        #pragma unroll
        for (int t = 0; t < 8; t++)
            #pragma unroll
            for (int q = 0; q < 4; q++) O[a][t][q] = 0.f;
    }

    const int lrw = lane & 15;
    const int lhc = lane >> 4;
    const int vm  = lane >> 3;
    const int vr  = lane & 7;

    const int NT = SEQ / AT_BK;
    for (int kt = 0; kt < NT; kt++) {
        CP_WAIT1();
        __syncthreads();
        const uint32_t st = sb + AT_SBASE + (uint32_t)(kt & 1)*AT_STAGE;
        const uint32_t Vh = st + 4*AT_KT, Vl = st + 5*AT_KT;

        #pragma unroll
        for (int a = 0; a < 2; a++) {
            const uint32_t Kh = st + (uint32_t)(a*2)*AT_KT;
            const uint32_t Kl = Kh + AT_KT;
            const uint32_t Qh = sb + (uint32_t)(a*2)*AT_QT;
            const uint32_t Ql = Qh + AT_QT;

            float s[8][4];
            #pragma unroll
            for (int j = 0; j < 8; j++)
                #pragma unroll
                for (int q = 0; q < 4; q++) s[j][q] = 0.f;

            #pragma unroll
            for (int hh = 0; hh < 4; hh++) {
                const int c = hh*2 + lhc;
                const uint32_t qoff = ASW(wid*16 + lrw, c);
                uint32_t ah0,ah1,ah2,ah3, al0,al1,al2,al3;
                ldsm4(ah0,ah1,ah2,ah3, Qh + qoff);
                ldsm4(al0,al1,al2,al3, Ql + qoff);
                uint32_t bh[8][2], bl[8][2];
                #pragma unroll
                for (int u = 0; u < 4; u++) {
                    const uint32_t koff = ASW(u*16 + lrw, c);
                    uint32_t r0,r1,r2,r3;
                    ldsm4(r0,r1,r2,r3, Kh + koff);
                    bh[2*u][0]=r0; bh[2*u][1]=r2; bh[2*u+1][0]=r1; bh[2*u+1][1]=r3;
                    ldsm4(r0,r1,r2,r3, Kl + koff);
                    bl[2*u][0]=r0; bl[2*u][1]=r2; bl[2*u+1][0]=r1; bl[2*u+1][1]=r3;
                }
                #pragma unroll
                for (int j = 0; j < 8; j++) {
                    mma16816(s[j][0],s[j][1],s[j][2],s[j][3], ah0,ah1,ah2,ah3, bh[j][0],bh[j][1]);
                    mma16816(s[j][0],s[j][1],s[j][2],s[j][3], ah0,ah1,ah2,ah3, bl[j][0],bl[j][1]);
                    mma16816(s[j][0],s[j][1],s[j][2],s[j][3], al0,al1,al2,al3, bh[j][0],bh[j][1]);
                }
            }

            float rm0 = -1e30f, rm1 = -1e30f;
            #pragma unroll
            for (int j = 0; j < 8; j++) {
                #pragma unroll
                for (int q = 0; q < 4; q++) {
                    float v = fminf(fmaxf(s[j][q]*0.125f, -ATTN_CLIP), ATTN_CLIP);
                    s[j][q] = v;
                }
                rm0 = fmaxf(rm0, fmaxf(s[j][0], s[j][1]));
                rm1 = fmaxf(rm1, fmaxf(s[j][2], s[j][3]));
            }
            rm0 = fmaxf(rm0, __shfl_xor_sync(0xffffffffu, rm0, 1));
            rm0 = fmaxf(rm0, __shfl_xor_sync(0xffffffffu, rm0, 2));
            rm1 = fmaxf(rm1, __shfl_xor_sync(0xffffffffu, rm1, 1));
            rm1 = fmaxf(rm1, __shfl_xor_sync(0xffffffffu, rm1, 2));
            const float mn0 = fmaxf(mr[a][0], rm0);
            const float mn1 = fmaxf(mr[a][1], rm1);
            const float f0 = __expf(mr[a][0] - mn0);
            const float f1 = __expf(mr[a][1] - mn1);
            mr[a][0] = mn0; mr[a][1] = mn1;
            float sum0 = 0.f, sum1 = 0.f;
            #pragma unroll
            for (int j = 0; j < 8; j++) {
                s[j][0] = __expf(s[j][0] - mn0);
                s[j][1] = __expf(s[j][1] - mn0);
                s[j][2] = __expf(s[j][2] - mn1);
                s[j][3] = __expf(s[j][3] - mn1);
                sum0 += s[j][0] + s[j][1];
                sum1 += s[j][2] + s[j][3];
            }
            sum0 += __shfl_xor_sync(0xffffffffu, sum0, 1);
            sum0 += __shfl_xor_sync(0xffffffffu, sum0, 2);
            sum1 += __shfl_xor_sync(0xffffffffu, sum1, 1);
            sum1 += __shfl_xor_sync(0xffffffffu, sum1, 2);
            lr[a][0] = lr[a][0]*f0 + sum0;
            lr[a][1] = lr[a][1]*f1 + sum1;
            #pragma unroll
            for (int t = 0; t < 8; t++) {
                O[a][t][0] *= f0; O[a][t][1] *= f0;
                O[a][t][2] *= f1; O[a][t][3] *= f1;
            }

            uint32_t pah[4][4], pal[4][4];
            #pragma unroll
            for (int kk = 0; kk < 4; kk++) {
                const int j0 = 2*kk, j1 = 2*kk + 1;
                packsplit(s[j0][0], s[j0][1], pah[kk][0], pal[kk][0]);
                packsplit(s[j0][2], s[j0][3], pah[kk][1], pal[kk][1]);
                packsplit(s[j1][0], s[j1][1], pah[kk][2], pal[kk][2]);
                packsplit(s[j1][2], s[j1][3], pah[kk][3], pal[kk][3]);
            }

            #pragma unroll
            for (int kk = 0; kk < 4; kk++) {
                uint32_t vbh[8][2], vbl[8][2];
                #pragma unroll
                for (int np = 0; np < 4; np++) {
                    const int vrow = kk*16 + (vm & 1)*8 + vr;
                    const int vc   = np*2 + (vm >> 1);
                    const uint32_t off = ASW(vrow, vc);
                    uint32_t r0,r1,r2,r3;
                    ldsm4t(r0,r1,r2,r3, Vh + off);
                    vbh[2*np][0]=r0; vbh[2*np][1]=r1; vbh[2*np+1][0]=r2; vbh[2*np+1][1]=r3;
                    ldsm4t(r0,r1,r2,r3, Vl + off);
                    vbl[2*np][0]=r0; vbl[2*np][1]=r1; vbl[2*np+1][0]=r2; vbl[2*np+1][1]=r3;
                }
                #pragma unroll
                for (int t = 0; t < 8; t++) {
                    mma16816(O[a][t][0],O[a][t][1],O[a][t][2],O[a][t][3],
                             pah[kk][0],pah[kk][1],pah[kk][2],pah[kk][3], vbh[t][0],vbh[t][1]);
                    mma16816(O[a][t][0],O[a][t][1],O[a][t][2],O[a][t][3],
                             pah[kk][0],pah[kk][1],pah[kk][2],pah[kk][3], vbl[t][0],vbl[t][1]);
                    mma16816(O[a][t][0],O[a][t][1],O[a][t][2],O[a][t][3],
                             pal[kk][0],pal[kk][1],pal[kk][2],pal[kk][3], vbh[t][0],vbh[t][1]);
                }
            }
        }

        __syncthreads();
        if (kt + 2 < NT) {
            at_load_stage(st, tid, qh, ql, kbase + (size_t)(kt + 2)*AT_BK, hof);
            CP_COMMIT();
        }
    }

    const float lam = g_lam;
    const int r0 = wid*16 + (lane >> 2);
    #pragma unroll
    for (int hh = 0; hh < 2; hh++) {
        const float inv1 = 1.f / (lr[0][hh] + EPSV);
        const float inv2 = lam / (lr[1][hh] + EPSV);
        const size_t gr = grow0 + r0 + hh*8;
        #pragma unroll
        for (int t = 0; t < 8; t++) {
            float v0 = O[0][t][2*hh]   * inv1 - O[1][t][2*hh]   * inv2;
            float v1 = O[0][t][2*hh+1] * inv1 - O[1][t][2*hh+1] * inv2;
            uint32_t ph, pl;
            packsplit(v0, v1, ph, pl);
            const size_t o = gr*DIM + hof + t*8 + 2*(lane & 3);
            *(uint32_t*)(outh + o) = ph;
            *(uint32_t*)(outl + o) = pl;
        }
    }
}

// ---------------------------------------------------------------------------
// Launch
// ---------------------------------------------------------------------------
extern "C" void kernel_launch(void* const* d_in, const int* in_sizes, int n_in,
                              void* d_out, int out_size)
{
    const float* x      = (const float*)d_in[0];
    const float* w_qkv  = (const float*)d_in[1];
    const float* lq1    = (const float*)d_in[2];
    const float* lk1    = (const float*)d_in[3];
    const float* lq2    = (const float*)d_in[4];
    const float* lk2    = (const float*)d_in[5];
    const float* w_proj = (const float*)d_in[6];
    const float* b_proj = (const float*)d_in[7];
    const float* gamma1 = (const float*)d_in[8];
    const float* beta1  = (const float*)d_in[9];
    const float* gamma2 = (const float*)d_in[10];
    const float* beta2  = (const float*)d_in[11];
    const float* w1     = (const float*)d_in[12];
    const float* b1     = (const float*)d_in[13];
    const float* w2     = (const float*)d_in[14];
    const float* b2     = (const float*)d_in[15];
    float* out = (float*)d_out;

    __nv_bfloat16 *h1h,*h1l,*qvh,*qvl,*ath,*atl,*h2h,*h2l,*f1h,*f1l;
    __nv_bfloat16 *wqh,*wql,*wph,*wpl,*w1h,*w1l,*w2h,*w2l;
    float *x2p;
    cudaGetSymbolAddress((void**)&h1h, g_h1h); cudaGetSymbolAddress((void**)&h1l, g_h1l);
    cudaGetSymbolAddress((void**)&qvh, g_qvh); cudaGetSymbolAddress((void**)&qvl, g_qvl);
    cudaGetSymbolAddress((void**)&ath, g_ath); cudaGetSymbolAddress((void**)&atl, g_atl);
    cudaGetSymbolAddress((void**)&h2h, g_h2h); cudaGetSymbolAddress((void**)&h2l, g_h2l);
    cudaGetSymbolAddress((void**)&f1h, g_f1h); cudaGetSymbolAddress((void**)&f1l, g_f1l);
    cudaGetSymbolAddress((void**)&wqh, g_wqh); cudaGetSymbolAddress((void**)&wql, g_wql);
    cudaGetSymbolAddress((void**)&wph, g_wph); cudaGetSymbolAddress((void**)&wpl, g_wpl);
    cudaGetSymbolAddress((void**)&w1h, g_w1h); cudaGetSymbolAddress((void**)&w1l, g_w1l);
    cudaGetSymbolAddress((void**)&w2h, g_w2h); cudaGetSymbolAddress((void**)&w2l, g_w2l);
    cudaGetSymbolAddress((void**)&x2p,  g_x2);

    cudaFuncSetAttribute(hmma_gemm_kernel<0,0,0,0,1>, cudaFuncAttributeMaxDynamicSharedMemorySize, HG_SMEM);
    cudaFuncSetAttribute(hmma_gemm_kernel<1,1,0,1,0>, cudaFuncAttributeMaxDynamicSharedMemorySize, HG_SMEM);
    cudaFuncSetAttribute(hmma_gemm_kernel<1,0,1,0,1>, cudaFuncAttributeMaxDynamicSharedMemorySize, HG_SMEM);
    cudaFuncSetAttribute(diff_attn_mma_kernel, cudaFuncAttributeMaxDynamicSharedMemorySize, AT_SMEM);

    // weight transpose + split
    wtrans_kernel<<<dim3(QKVN/32, DIM/32), dim3(32,8)>>>(w_qkv,  wqh, wql, DIM, QKVN);
    wtrans_kernel<<<dim3(DIM/32,  DIM/32), dim3(32,8)>>>(w_proj, wph, wpl, DIM, DIM);
    wtrans_kernel<<<dim3(MLP/32,  DIM/32), dim3(32,8)>>>(w1,     w1h, w1l, DIM, MLP);
    wtrans_kernel<<<dim3(DIM/32,  MLP/32), dim3(32,8)>>>(w2,     w2h, w2l, MLP, DIM);

    // GRN1 -> h1 (bf16 split)
    reduce_sq_kernel<<<dim3(64, BATCH), 256>>>(x);
    grn_finalize_kernel<<<BATCH, 32>>>();
    grn_apply_split_kernel<<<ROWS*DIM/4/256, 256>>>(x, gamma1, beta1, h1h, h1l);

    // QKV GEMM -> bf16 hi/lo qkv
    hmma_gemm_kernel<0,0,0,0,1><<<dim3(QKVN/HG_NT, ROWS/HG_MT), 256, HG_SMEM>>>(
        h1h, h1l, wqh, wql, nullptr, nullptr, nullptr, qvh, qvl, ROWS, QKVN, DIM);

    lam_kernel<<<1, 32>>>(lq1, lk1, lq2, lk2);

    // differential attention (HMMA) -> attn (bf16 split)
    diff_attn_mma_kernel<<<dim3(SEQ/AT_BQ, NH, BATCH), 256, AT_SMEM>>>(qvh, qvl, ath, atl);

    // proj + bias + residual(x) -> x2 (fp32)
    hmma_gemm_kernel<1,1,0,1,0><<<dim3(DIM/HG_NT, ROWS/HG_MT), 256, HG_SMEM>>>(
        ath, atl, wph, wpl, b_proj, x, x2p, nullptr, nullptr, ROWS, DIM, DIM);

    // GRN2 -> h2 (bf16 split)
    reduce_sq_kernel<<<dim3(64, BATCH), 256>>>(x2p);
    grn_finalize_kernel<<<BATCH, 32>>>();
    grn_apply_split_kernel<<<ROWS*DIM/4/256, 256>>>(x2p, gamma2, beta2, h2h, h2l);

    // FFN1: silu(h2@w1+b1) -> ffn1 (bf16 split only)
    hmma_gemm_kernel<1,0,1,0,1><<<dim3(MLP/HG_NT, ROWS/HG_MT), 256, HG_SMEM>>>(
        h2h, h2l, w1h, w1l, b1, nullptr, nullptr, f1h, f1l, ROWS, MLP, DIM);

    // FFN2: ffn1@w2 + b2 + x2 -> out (fp32)
    hmma_gemm_kernel<1,1,0,1,0><<<dim3(DIM/HG_NT, ROWS/HG_MT), 256, HG_SMEM>>>(
        f1h, f1l, w2h, w2l, b2, x2p, out, nullptr, nullptr, ROWS, DIM, MLP);
}

// round 14
// speedup vs baseline: 1.1256x; 1.1256x over previous
#include <cuda_runtime.h>
#include <cuda_bf16.h>
#include <math.h>
#include <cstdint>

// ---------------------------------------------------------------------------
// Problem constants
// ---------------------------------------------------------------------------
#define BATCH   4
#define SEQ     1024
#define DIM     1024
#define NH      16
#define HD      64
#define MLP     4096
#define ROWS    (BATCH*SEQ)       // 4096
#define QKVN    (5*NH*HD)         // 5120
#define EPSV    1e-6f
#define ATTN_CLIP 100.0f
#define NORM_CLIP 1000.0f

// ---------------------------------------------------------------------------
// PTX helpers — ONLY plain-sm_103-legal features: cp.async, ldmatrix, mma.sync
// ---------------------------------------------------------------------------
__device__ __forceinline__ uint32_t smem_to_u32(const void* p) {
    uint32_t a;
    asm("{ .reg .u64 t; cvta.to.shared.u64 t, %1; cvt.u32.u64 %0, t; }" : "=r"(a) : "l"(p));
    return a;
}
#define CP_ASYNC16(dst, src) \
    asm volatile("cp.async.cg.shared.global [%0], [%1], 16;" :: "r"(dst), "l"(src) : "memory")
#define CP_COMMIT() asm volatile("cp.async.commit_group;" ::: "memory")
#define CP_WAIT1()  asm volatile("cp.async.wait_group 1;" ::: "memory")

__device__ __forceinline__ void ldsm4(uint32_t& r0, uint32_t& r1, uint32_t& r2, uint32_t& r3,
                                      uint32_t addr) {
    asm volatile("ldmatrix.sync.aligned.m8n8.x4.shared.b16 {%0,%1,%2,%3}, [%4];"
                 : "=r"(r0), "=r"(r1), "=r"(r2), "=r"(r3) : "r"(addr));
}
__device__ __forceinline__ void ldsm4t(uint32_t& r0, uint32_t& r1, uint32_t& r2, uint32_t& r3,
                                       uint32_t addr) {
    asm volatile("ldmatrix.sync.aligned.m8n8.x4.trans.shared.b16 {%0,%1,%2,%3}, [%4];"
                 : "=r"(r0), "=r"(r1), "=r"(r2), "=r"(r3) : "r"(addr));
}
__device__ __forceinline__ void mma16816(float& c0, float& c1, float& c2, float& c3,
                                         uint32_t a0, uint32_t a1, uint32_t a2, uint32_t a3,
                                         uint32_t b0, uint32_t b1) {
    asm volatile("mma.sync.aligned.m16n8k16.row.col.f32.bf16.bf16.f32 "
                 "{%0,%1,%2,%3}, {%4,%5,%6,%7}, {%8,%9}, {%0,%1,%2,%3};"
                 : "+f"(c0), "+f"(c1), "+f"(c2), "+f"(c3)
                 : "r"(a0), "r"(a1), "r"(a2), "r"(a3), "r"(b0), "r"(b1));
}

__device__ __forceinline__ void split2(float v, __nv_bfloat16& h, __nv_bfloat16& l) {
    h = __float2bfloat16(v);
    l = __float2bfloat16(v - __bfloat162float(h));
}
__device__ __forceinline__ uint32_t bf16bits(__nv_bfloat16 h) {
    unsigned short u; memcpy(&u, &h, 2); return (uint32_t)u;
}
__device__ __forceinline__ void packsplit(float a, float b, uint32_t& hi, uint32_t& lo) {
    __nv_bfloat16 ah, al, bh, bl;
    split2(a, ah, al); split2(b, bh, bl);
    hi = bf16bits(ah) | (bf16bits(bh) << 16);
    lo = bf16bits(al) | (bf16bits(bl) << 16);
}

// ---------------------------------------------------------------------------
// Scratch (static device globals)
// ---------------------------------------------------------------------------
__device__ __nv_bfloat16 g_h1h[ROWS*DIM],  g_h1l[ROWS*DIM];
__device__ __nv_bfloat16 g_qvh[ROWS*QKVN], g_qvl[ROWS*QKVN];
__device__ __nv_bfloat16 g_ath[ROWS*DIM],  g_atl[ROWS*DIM];
__device__ float         g_x2 [ROWS*DIM];
__device__ __nv_bfloat16 g_h2h[ROWS*DIM],  g_h2l[ROWS*DIM];
__device__ __nv_bfloat16 g_f1h[ROWS*MLP],  g_f1l[ROWS*MLP];
__device__ __nv_bfloat16 g_wqh[QKVN*DIM],  g_wql[QKVN*DIM];
__device__ __nv_bfloat16 g_wph[DIM*DIM],   g_wpl[DIM*DIM];
__device__ __nv_bfloat16 g_w1h[MLP*DIM],   g_w1l[MLP*DIM];
__device__ __nv_bfloat16 g_w2h[DIM*MLP],   g_w2l[DIM*MLP];
__device__ float g_part[BATCH*64];
__device__ float g_nx  [BATCH];
__device__ float g_lam;

// ---------------------------------------------------------------------------
// GRN reductions
// ---------------------------------------------------------------------------
__global__ void reduce_sq_kernel(const float* __restrict__ x)
{
    const int b   = blockIdx.y;
    const int tid = threadIdx.x;
    const float4* xb = (const float4*)(x + (size_t)b * (SEQ*DIM));
    const int n4 = SEQ*DIM/4;
    float s = 0.f;
    for (int i = blockIdx.x*blockDim.x + tid; i < n4; i += gridDim.x*blockDim.x) {
        float4 v = xb[i];
        s += v.x*v.x + v.y*v.y + v.z*v.z + v.w*v.w;
    }
    #pragma unroll
    for (int o = 16; o; o >>= 1) s += __shfl_xor_sync(0xffffffffu, s, o);
    __shared__ float ws[8];
    if ((tid & 31) == 0) ws[tid >> 5] = s;
    __syncthreads();
    if (tid < 8) {
        s = ws[tid];
        #pragma unroll
        for (int o = 4; o; o >>= 1) s += __shfl_xor_sync(0xffu, s, o);
        if (tid == 0) g_part[b*64 + blockIdx.x] = s;
    }
}

__global__ void grn_finalize_kernel()
{
    const int b = blockIdx.x, t = threadIdx.x;
    float s = g_part[b*64 + t] + g_part[b*64 + t + 32];
    #pragma unroll
    for (int o = 16; o; o >>= 1) s += __shfl_xor_sync(0xffffffffu, s, o);
    if (t == 0) {
        float ss = fminf(fmaxf(s, EPSV), NORM_CLIP);
        float gx = sqrtf(ss);
        float nx = gx / (gx + EPSV);
        nx = fminf(fmaxf(nx, -NORM_CLIP), NORM_CLIP);
        g_nx[b] = nx;
    }
}

__global__ void grn_apply_split_kernel(const float* __restrict__ x,
                                       const float* __restrict__ gamma,
                                       const float* __restrict__ beta,
                                       __nv_bfloat16* __restrict__ hi,
                                       __nv_bfloat16* __restrict__ lo)
{
    const int i  = blockIdx.x*blockDim.x + threadIdx.x;
    const int n4 = ROWS*DIM/4;
    if (i >= n4) return;
    const int d4 = i & (DIM/4 - 1);
    const int b  = i / (SEQ*DIM/4);
    const float nx = g_nx[b];
    float4 xv = ((const float4*)x)[i];
    float4 gv = ((const float4*)gamma)[d4];
    float4 bv = ((const float4*)beta)[d4];
    float r0 = gv.x*(xv.x*nx) + bv.x + xv.x;
    float r1 = gv.y*(xv.y*nx) + bv.y + xv.y;
    float r2 = gv.z*(xv.z*nx) + bv.z + xv.z;
    float r3 = gv.w*(xv.w*nx) + bv.w + xv.w;
    __align__(8) __nv_bfloat16 hb[4], lb[4];
    split2(r0, hb[0], lb[0]); split2(r1, hb[1], lb[1]);
    split2(r2, hb[2], lb[2]); split2(r3, hb[3], lb[3]);
    ((uint2*)hi)[i] = *(uint2*)hb;
    ((uint2*)lo)[i] = *(uint2*)lb;
}

// ---------------------------------------------------------------------------
// Weight transpose + bf16 split: w[K,N] -> hi/lo[N,K]
// ---------------------------------------------------------------------------
__global__ void wtrans_kernel(const float* __restrict__ w,
                              __nv_bfloat16* __restrict__ hi,
                              __nv_bfloat16* __restrict__ lo, int K, int N)
{
    __shared__ float t[32][33];
    const int n0 = blockIdx.x << 5, k0 = blockIdx.y << 5;
    const int tx = threadIdx.x, ty = threadIdx.y;
    #pragma unroll
    for (int i = ty; i < 32; i += 8)
        t[i][tx] = w[(size_t)(k0 + i)*N + n0 + tx];
    __syncthreads();
    #pragma unroll
    for (int i = ty; i < 32; i += 8) {
        float v = t[tx][i];
        __nv_bfloat16 h, l;
        split2(v, h, l);
        size_t o = (size_t)(n0 + i)*K + k0 + tx;
        hi[o] = h; lo[o] = l;
    }
}

// ---------------------------------------------------------------------------
// lambda scalar
// ---------------------------------------------------------------------------
__global__ void lam_kernel(const float* __restrict__ lq1, const float* __restrict__ lk1,
                           const float* __restrict__ lq2, const float* __restrict__ lk2)
{
    const int t = threadIdx.x;
    float a = lq1[t]*lk1[t] + lq1[t+32]*lk1[t+32];
    float c = lq2[t]*lk2[t] + lq2[t+32]*lk2[t+32];
    #pragma unroll
    for (int o = 16; o; o >>= 1) {
        a += __shfl_xor_sync(0xffffffffu, a, o);
        c += __shfl_xor_sync(0xffffffffu, c, o);
    }
    if (t == 0) {
        float l1 = fminf(fmaxf(a, -10.f), 10.f);
        float l2 = fminf(fmaxf(c, -10.f), 10.f);
        g_lam = fminf(fmaxf(expf(l1) - expf(l2) + 0.2f, 0.1f), 5.0f);
    }
}

// ---------------------------------------------------------------------------
// HMMA GEMM (measured-best R8 config):
// CTA 128x128, BK=32, 3-stage cp.async pipeline, 8 warps x (64x32) warp tile.
// ---------------------------------------------------------------------------
#define HG_MT 128
#define HG_NT 128
#define HG_BK 32
#define HG_TILE  8192
#define HG_STAGE (4*HG_TILE)
#define HG_SMEM  (3*HG_STAGE)

__device__ __forceinline__ void hg_load_tile(uint32_t sbase, int tid,
    const __nv_bfloat16* __restrict__ g, int rbase, int K, int kt)
{
    #pragma unroll
    for (int it = 0; it < 2; it++) {
        int f   = tid + it*256;
        int row = f >> 2, c = f & 3;
        int sw  = c ^ ((row >> 1) & 3);
        uint32_t sa = sbase + (uint32_t)(row*64 + sw*16);
        CP_ASYNC16(sa, g + (size_t)(rbase + row)*K + kt + c*8);
    }
}

__device__ __forceinline__ void hg_load_stage(uint32_t sbase, int tid,
    const __nv_bfloat16* __restrict__ Ahi, const __nv_bfloat16* __restrict__ Alo,
    const __nv_bfloat16* __restrict__ Bhi, const __nv_bfloat16* __restrict__ Blo,
    int row0, int col0, int K, int kt)
{
    hg_load_tile(sbase,             tid, Ahi, row0, K, kt);
    hg_load_tile(sbase +   HG_TILE, tid, Alo, row0, K, kt);
    hg_load_tile(sbase + 2*HG_TILE, tid, Bhi, col0, K, kt);
    hg_load_tile(sbase + 3*HG_TILE, tid, Blo, col0, K, kt);
}

template<int DO_BIAS, int DO_RES, int DO_SILU, int OUT_F32, int OUT_SPLIT>
__global__ __launch_bounds__(256, 1)
void hmma_gemm_kernel(
    const __nv_bfloat16* __restrict__ Ahi, const __nv_bfloat16* __restrict__ Alo,
    const __nv_bfloat16* __restrict__ Bhi, const __nv_bfloat16* __restrict__ Blo,
    const float* __restrict__ bias, const float* __restrict__ res,
    float* __restrict__ Cf, __nv_bfloat16* __restrict__ Chi, __nv_bfloat16* __restrict__ Clo,
    int M, int N, int K)
{
    extern __shared__ char smem[];
    const uint32_t sb = smem_to_u32(smem);
    const int tid  = threadIdx.x;
    const int wid  = tid >> 5;
    const int lane = tid & 31;
    const int wm   = (wid & 1) << 6;
    const int wn   = (wid >> 1) << 5;
    const int row0 = blockIdx.y * HG_MT;
    const int col0 = blockIdx.x * HG_NT;

    float acc[4][4][4];
    #pragma unroll
    for (int i = 0; i < 4; i++)
        #pragma unroll
        for (int j = 0; j < 4; j++)
            #pragma unroll
            for (int q = 0; q < 4; q++) acc[i][j][q] = 0.f;

    const int S = K / HG_BK;
    hg_load_stage(sb, tid, Ahi, Alo, Bhi, Blo, row0, col0, K, 0);
    CP_COMMIT();
    hg_load_stage(sb + HG_STAGE, tid, Ahi, Alo, Bhi, Blo, row0, col0, K, HG_BK);
    CP_COMMIT();

    const int lrow = lane & 15;
    const int lhi  = lane >> 4;

    int buf = 0;
    for (int i = 0; i < S; i++) {
        CP_WAIT1();
        __syncthreads();
        if (i + 2 < S)
            hg_load_stage(sb + ((buf + 2) % 3)*HG_STAGE, tid, Ahi, Alo, Bhi, Blo,
                          row0, col0, K, (i + 2)*HG_BK);
        CP_COMMIT();

        const uint32_t bA  = sb + buf*HG_STAGE;
        const uint32_t bAl = bA + HG_TILE;
        const uint32_t bB  = bA + 2*HG_TILE;
        const uint32_t bBl = bA + 3*HG_TILE;

        #pragma unroll
        for (int h = 0; h < 2; h++) {
            uint32_t ah[4][4], al[4][4], bh[4][2], bl[4][2];
            #pragma unroll
            for (int tm = 0; tm < 4; tm++) {
                int row = wm + tm*16 + lrow;
                int c   = h*2 + lhi;
                uint32_t off = (uint32_t)(row*64 + ((c ^ ((row >> 1) & 3))*16));
                ldsm4(ah[tm][0], ah[tm][1], ah[tm][2], ah[tm][3], bA  + off);
                ldsm4(al[tm][0], al[tm][1], al[tm][2], al[tm][3], bAl + off);
            }
            #pragma unroll
            for (int u = 0; u < 2; u++) {
                int row = wn + u*16 + lrow;
                int c   = h*2 + lhi;
                uint32_t off = (uint32_t)(row*64 + ((c ^ ((row >> 1) & 3))*16));
                uint32_t r0, r1, r2, r3;
                ldsm4(r0, r1, r2, r3, bB + off);
                bh[2*u][0] = r0; bh[2*u][1] = r2; bh[2*u+1][0] = r1; bh[2*u+1][1] = r3;
                ldsm4(r0, r1, r2, r3, bBl + off);
                bl[2*u][0] = r0; bl[2*u][1] = r2; bl[2*u+1][0] = r1; bl[2*u+1][1] = r3;
            }
            #pragma unroll
            for (int tm = 0; tm < 4; tm++)
                #pragma unroll
                for (int tn = 0; tn < 4; tn++) {
                    mma16816(acc[tm][tn][0], acc[tm][tn][1], acc[tm][tn][2], acc[tm][tn][3],
                             ah[tm][0], ah[tm][1], ah[tm][2], ah[tm][3], bh[tn][0], bh[tn][1]);
                    mma16816(acc[tm][tn][0], acc[tm][tn][1], acc[tm][tn][2], acc[tm][tn][3],
                             ah[tm][0], ah[tm][1], ah[tm][2], ah[tm][3], bl[tn][0], bl[tn][1]);
                    mma16816(acc[tm][tn][0], acc[tm][tn][1], acc[tm][tn][2], acc[tm][tn][3],
                             al[tm][0], al[tm][1], al[tm][2], al[tm][3], bh[tn][0], bh[tn][1]);
                }
        }
        buf = (buf + 1) % 3;
    }

    #pragma unroll
    for (int tm = 0; tm < 4; tm++) {
        #pragma unroll
        for (int tn = 0; tn < 4; tn++) {
            const int gr0 = row0 + wm + tm*16 + (lane >> 2);
            const int gc  = col0 + wn + tn*8 + 2*(lane & 3);
            #pragma unroll
            for (int hh = 0; hh < 2; hh++) {
                const int gr = gr0 + hh*8;
                float v0 = acc[tm][tn][2*hh];
                float v1 = acc[tm][tn][2*hh + 1];
                if (DO_BIAS) { v0 += bias[gc]; v1 += bias[gc + 1]; }
                if (DO_SILU) {
                    v0 = v0 / (1.f + __expf(-v0));
                    v1 = v1 / (1.f + __expf(-v1));
                }
                if (DO_RES) {
                    float2 rv = *(const float2*)(res + (size_t)gr*N + gc);
                    v0 += rv.x; v1 += rv.y;
                }
                if (OUT_F32)
                    *(float2*)(Cf + (size_t)gr*N + gc) = make_float2(v0, v1);
                if (OUT_SPLIT) {
                    __align__(4) __nv_bfloat16 hp[2], lp[2];
                    split2(v0, hp[0], lp[0]); split2(v1, hp[1], lp[1]);
                    *(uint32_t*)(Chi + (size_t)gr*N + gc) = *(uint32_t*)hp;
                    *(uint32_t*)(Clo + (size_t)gr*N + gc) = *(uint32_t*)lp;
                }
            }
        }
    }
}

// ---------------------------------------------------------------------------
// HMMA differential flash-attention.
// R13 change vs R8: V fragments hoisted — P for BOTH attentions is computed
// first, then a single kk loop loads V fragments once and feeds both O[a].
// Per-O accumulation order unchanged -> bit-identical results.
// ---------------------------------------------------------------------------
#define AT_BQ   128
#define AT_BK   64
#define AT_QT   (AT_BQ*128)
#define AT_KT   (AT_BK*128)
#define AT_SBASE (4*AT_QT)
#define AT_STAGE (6*AT_KT)
#define AT_SMEM  (AT_SBASE + 2*AT_STAGE)
#define ASW(row, c) ((uint32_t)((row)*128 + (((c) ^ ((row) & 7))*16)))

__device__ __forceinline__ void at_load_stage(uint32_t base, int tid,
    const __nv_bfloat16* __restrict__ qh, const __nv_bfloat16* __restrict__ ql,
    size_t krow0, int hof)
{
    #pragma unroll
    for (int i = 0; i < 12; i++) {
        int f = tid + i*256;
        int tile = f >> 9, rem = f & 511;
        int row = rem >> 3, c = rem & 7;
        const __nv_bfloat16* src = (tile & 1) ? ql : qh;
        int off = (tile < 4) ? (2 + (tile >> 1))*NH*HD : 4*NH*HD;
        CP_ASYNC16(base + tile*AT_KT + ASW(row, c),
                   src + (krow0 + row)*QKVN + hof + off + c*8);
    }
}

__global__ __launch_bounds__(256, 1) void diff_attn_mma_kernel(
    const __nv_bfloat16* __restrict__ qh, const __nv_bfloat16* __restrict__ ql,
    __nv_bfloat16* __restrict__ outh, __nv_bfloat16* __restrict__ outl)
{
    extern __shared__ char smem[];
    const uint32_t sb = smem_to_u32(smem);
    const int tid = threadIdx.x, wid = tid >> 5, lane = tid & 31;
    const int q0  = blockIdx.x * AT_BQ;
    const int hof = blockIdx.y * HD;
    const int b   = blockIdx.z;
    const size_t grow0 = (size_t)(b*SEQ + q0);
    const size_t kbase = (size_t)(b*SEQ);

    #pragma unroll
    for (int i = 0; i < 16; i++) {
        int f = tid + i*256;
        int tile = f >> 10, rem = f & 1023;
        int row = rem >> 3, c = rem & 7;
        const __nv_bfloat16* src = (tile & 1) ? ql : qh;
        int off = (tile >> 1) ? NH*HD : 0;
        CP_ASYNC16(sb + tile*AT_QT + ASW(row, c),
                   src + (grow0 + row)*QKVN + hof + off + c*8);
    }
    at_load_stage(sb + AT_SBASE, tid, qh, ql, kbase, hof);
    CP_COMMIT();
    at_load_stage(sb + AT_SBASE + AT_STAGE, tid, qh, ql, kbase + AT_BK, hof);
    CP_COMMIT();

    float O[2][8][4];
    float mr[2][2], lr[2][2];
    #pragma unroll
    for (int a = 0; a < 2; a++) {
        mr[a][0] = -1e30f; mr[a][1] = -1e30f; lr[a][0] = 0.f; lr[a][1] = 0.f;
        #pragma unroll
        for (int t = 0; t < 8; t++)
            #pragma unroll
            for (int q = 0; q < 4; q++) O[a][t][q] = 0.f;
    }

    const int lrw = lane & 15;
    const int lhc = lane >> 4;
    const int vm  = lane >> 3;
    const int vr  = lane & 7;

    const int NT = SEQ / AT_BK;
    for (int kt = 0; kt < NT; kt++) {
        CP_WAIT1();
        __syncthreads();
        const uint32_t st = sb + AT_SBASE + (uint32_t)(kt & 1)*AT_STAGE;
        const uint32_t Vh = st + 4*AT_KT, Vl = st + 5*AT_KT;

        uint32_t pah[2][4][4], pal[2][4][4];   // P fragments for BOTH attentions

        #pragma unroll
        for (int a = 0; a < 2; a++) {
            const uint32_t Kh = st + (uint32_t)(a*2)*AT_KT;
            const uint32_t Kl = Kh + AT_KT;
            const uint32_t Qh = sb + (uint32_t)(a*2)*AT_QT;
            const uint32_t Ql = Qh + AT_QT;

            float s[8][4];
            #pragma unroll
            for (int j = 0; j < 8; j++)
                #pragma unroll
                for (int q = 0; q < 4; q++) s[j][q] = 0.f;

            #pragma unroll
            for (int hh = 0; hh < 4; hh++) {
                const int c = hh*2 + lhc;
                const uint32_t qoff = ASW(wid*16 + lrw, c);
                uint32_t ah0,ah1,ah2,ah3, al0,al1,al2,al3;
                ldsm4(ah0,ah1,ah2,ah3, Qh + qoff);
                ldsm4(al0,al1,al2,al3, Ql + qoff);
                uint32_t bh[8][2], bl[8][2];
                #pragma unroll
                for (int u = 0; u < 4; u++) {
                    const uint32_t koff = ASW(u*16 + lrw, c);
                    uint32_t r0,r1,r2,r3;
                    ldsm4(r0,r1,r2,r3, Kh + koff);
                    bh[2*u][0]=r0; bh[2*u][1]=r2; bh[2*u+1][0]=r1; bh[2*u+1][1]=r3;
                    ldsm4(r0,r1,r2,r3, Kl + koff);
                    bl[2*u][0]=r0; bl[2*u][1]=r2; bl[2*u+1][0]=r1; bl[2*u+1][1]=r3;
                }
                #pragma unroll
                for (int j = 0; j < 8; j++) {
                    mma16816(s[j][0],s[j][1],s[j][2],s[j][3], ah0,ah1,ah2,ah3, bh[j][0],bh[j][1]);
                    mma16816(s[j][0],s[j][1],s[j][2],s[j][3], ah0,ah1,ah2,ah3, bl[j][0],bl[j][1]);
                    mma16816(s[j][0],s[j][1],s[j][2],s[j][3], al0,al1,al2,al3, bh[j][0],bh[j][1]);
                }
            }

            float rm0 = -1e30f, rm1 = -1e30f;
            #pragma unroll
            for (int j = 0; j < 8; j++) {
                #pragma unroll
                for (int q = 0; q < 4; q++) {
                    float v = fminf(fmaxf(s[j][q]*0.125f, -ATTN_CLIP), ATTN_CLIP);
                    s[j][q] = v;
                }
                rm0 = fmaxf(rm0, fmaxf(s[j][0], s[j][1]));
                rm1 = fmaxf(rm1, fmaxf(s[j][2], s[j][3]));
            }
            rm0 = fmaxf(rm0, __shfl_xor_sync(0xffffffffu, rm0, 1));
            rm0 = fmaxf(rm0, __shfl_xor_sync(0xffffffffu, rm0, 2));
            rm1 = fmaxf(rm1, __shfl_xor_sync(0xffffffffu, rm1, 1));
            rm1 = fmaxf(rm1, __shfl_xor_sync(0xffffffffu, rm1, 2));
            const float mn0 = fmaxf(mr[a][0], rm0);
            const float mn1 = fmaxf(mr[a][1], rm1);
            const float f0 = __expf(mr[a][0] - mn0);
            const float f1 = __expf(mr[a][1] - mn1);
            mr[a][0] = mn0; mr[a][1] = mn1;
            float sum0 = 0.f, sum1 = 0.f;
            #pragma unroll
            for (int j = 0; j < 8; j++) {
                s[j][0] = __expf(s[j][0] - mn0);
                s[j][1] = __expf(s[j][1] - mn0);
                s[j][2] = __expf(s[j][2] - mn1);
                s[j][3] = __expf(s[j][3] - mn1);
                sum0 += s[j][0] + s[j][1];
                sum1 += s[j][2] + s[j][3];
            }
            sum0 += __shfl_xor_sync(0xffffffffu, sum0, 1);
            sum0 += __shfl_xor_sync(0xffffffffu, sum0, 2);
            sum1 += __shfl_xor_sync(0xffffffffu, sum1, 1);
            sum1 += __shfl_xor_sync(0xffffffffu, sum1, 2);
            lr[a][0] = lr[a][0]*f0 + sum0;
            lr[a][1] = lr[a][1]*f1 + sum1;
            #pragma unroll
            for (int t = 0; t < 8; t++) {
                O[a][t][0] *= f0; O[a][t][1] *= f0;
                O[a][t][2] *= f1; O[a][t][3] *= f1;
            }

            #pragma unroll
            for (int kk = 0; kk < 4; kk++) {
                const int j0 = 2*kk, j1 = 2*kk + 1;
                packsplit(s[j0][0], s[j0][1], pah[a][kk][0], pal[a][kk][0]);
                packsplit(s[j0][2], s[j0][3], pah[a][kk][1], pal[a][kk][1]);
                packsplit(s[j1][0], s[j1][1], pah[a][kk][2], pal[a][kk][2]);
                packsplit(s[j1][2], s[j1][3], pah[a][kk][3], pal[a][kk][3]);
            }
        }

        // ---- O[a] += P[a] V — V fragments loaded ONCE, shared across a ----
        #pragma unroll
        for (int kk = 0; kk < 4; kk++) {
            uint32_t vbh[8][2], vbl[8][2];
            #pragma unroll
            for (int np = 0; np < 4; np++) {
                const int vrow = kk*16 + (vm & 1)*8 + vr;
                const int vc   = np*2 + (vm >> 1);
                const uint32_t off = ASW(vrow, vc);
                uint32_t r0,r1,r2,r3;
                ldsm4t(r0,r1,r2,r3, Vh + off);
                vbh[2*np][0]=r0; vbh[2*np][1]=r1; vbh[2*np+1][0]=r2; vbh[2*np+1][1]=r3;
                ldsm4t(r0,r1,r2,r3, Vl + off);
                vbl[2*np][0]=r0; vbl[2*np][1]=r1; vbl[2*np+1][0]=r2; vbl[2*np+1][1]=r3;
            }
            #pragma unroll
            for (int a = 0; a < 2; a++)
                #pragma unroll
                for (int t = 0; t < 8; t++) {
                    mma16816(O[a][t][0],O[a][t][1],O[a][t][2],O[a][t][3],
                             pah[a][kk][0],pah[a][kk][1],pah[a][kk][2],pah[a][kk][3],
                             vbh[t][0],vbh[t][1]);
                    mma16816(O[a][t][0],O[a][t][1],O[a][t][2],O[a][t][3],
                             pah[a][kk][0],pah[a][kk][1],pah[a][kk][2],pah[a][kk][3],
                             vbl[t][0],vbl[t][1]);
                    mma16816(O[a][t][0],O[a][t][1],O[a][t][2],O[a][t][3],
                             pal[a][kk][0],pal[a][kk][1],pal[a][kk][2],pal[a][kk][3],
                             vbh[t][0],vbh[t][1]);
                }
        }

        __syncthreads();
        if (kt + 2 < NT) {
            at_load_stage(st, tid, qh, ql, kbase + (size_t)(kt + 2)*AT_BK, hof);
            CP_COMMIT();
        }
    }

    const float lam = g_lam;
    const int r0 = wid*16 + (lane >> 2);
    #pragma unroll
    for (int hh = 0; hh < 2; hh++) {
        const float inv1 = 1.f / (lr[0][hh] + EPSV);
        const float inv2 = lam / (lr[1][hh] + EPSV);
        const size_t gr = grow0 + r0 + hh*8;
        #pragma unroll
        for (int t = 0; t < 8; t++) {
            float v0 = O[0][t][2*hh]   * inv1 - O[1][t][2*hh]   * inv2;
            float v1 = O[0][t][2*hh+1] * inv1 - O[1][t][2*hh+1] * inv2;
            uint32_t ph, pl;
            packsplit(v0, v1, ph, pl);
            const size_t o = gr*DIM + hof + t*8 + 2*(lane & 3);
            *(uint32_t*)(outh + o) = ph;
            *(uint32_t*)(outl + o) = pl;
        }
    }
}

// ---------------------------------------------------------------------------
// Launch
// ---------------------------------------------------------------------------
extern "C" void kernel_launch(void* const* d_in, const int* in_sizes, int n_in,
                              void* d_out, int out_size)
{
    const float* x      = (const float*)d_in[0];
    const float* w_qkv  = (const float*)d_in[1];
    const float* lq1    = (const float*)d_in[2];
    const float* lk1    = (const float*)d_in[3];
    const float* lq2    = (const float*)d_in[4];
    const float* lk2    = (const float*)d_in[5];
    const float* w_proj = (const float*)d_in[6];
    const float* b_proj = (const float*)d_in[7];
    const float* gamma1 = (const float*)d_in[8];
    const float* beta1  = (const float*)d_in[9];
    const float* gamma2 = (const float*)d_in[10];
    const float* beta2  = (const float*)d_in[11];
    const float* w1     = (const float*)d_in[12];
    const float* b1     = (const float*)d_in[13];
    const float* w2     = (const float*)d_in[14];
    const float* b2     = (const float*)d_in[15];
    float* out = (float*)d_out;

    __nv_bfloat16 *h1h,*h1l,*qvh,*qvl,*ath,*atl,*h2h,*h2l,*f1h,*f1l;
    __nv_bfloat16 *wqh,*wql,*wph,*wpl,*w1h,*w1l,*w2h,*w2l;
    float *x2p;
    cudaGetSymbolAddress((void**)&h1h, g_h1h); cudaGetSymbolAddress((void**)&h1l, g_h1l);
    cudaGetSymbolAddress((void**)&qvh, g_qvh); cudaGetSymbolAddress((void**)&qvl, g_qvl);
    cudaGetSymbolAddress((void**)&ath, g_ath); cudaGetSymbolAddress((void**)&atl, g_atl);
    cudaGetSymbolAddress((void**)&h2h, g_h2h); cudaGetSymbolAddress((void**)&h2l, g_h2l);
    cudaGetSymbolAddress((void**)&f1h, g_f1h); cudaGetSymbolAddress((void**)&f1l, g_f1l);
    cudaGetSymbolAddress((void**)&wqh, g_wqh); cudaGetSymbolAddress((void**)&wql, g_wql);
    cudaGetSymbolAddress((void**)&wph, g_wph); cudaGetSymbolAddress((void**)&wpl, g_wpl);
    cudaGetSymbolAddress((void**)&w1h, g_w1h); cudaGetSymbolAddress((void**)&w1l, g_w1l);
    cudaGetSymbolAddress((void**)&w2h, g_w2h); cudaGetSymbolAddress((void**)&w2l, g_w2l);
    cudaGetSymbolAddress((void**)&x2p,  g_x2);

    cudaFuncSetAttribute(hmma_gemm_kernel<0,0,0,0,1>, cudaFuncAttributeMaxDynamicSharedMemorySize, HG_SMEM);
    cudaFuncSetAttribute(hmma_gemm_kernel<1,1,0,1,0>, cudaFuncAttributeMaxDynamicSharedMemorySize, HG_SMEM);
    cudaFuncSetAttribute(hmma_gemm_kernel<1,0,1,0,1>, cudaFuncAttributeMaxDynamicSharedMemorySize, HG_SMEM);
    cudaFuncSetAttribute(diff_attn_mma_kernel, cudaFuncAttributeMaxDynamicSharedMemorySize, AT_SMEM);

    // weight transpose + split
    wtrans_kernel<<<dim3(QKVN/32, DIM/32), dim3(32,8)>>>(w_qkv,  wqh, wql, DIM, QKVN);
    wtrans_kernel<<<dim3(DIM/32,  DIM/32), dim3(32,8)>>>(w_proj, wph, wpl, DIM, DIM);
    wtrans_kernel<<<dim3(MLP/32,  DIM/32), dim3(32,8)>>>(w1,     w1h, w1l, DIM, MLP);
    wtrans_kernel<<<dim3(DIM/32,  MLP/32), dim3(32,8)>>>(w2,     w2h, w2l, MLP, DIM);

    // GRN1 -> h1 (bf16 split)
    reduce_sq_kernel<<<dim3(64, BATCH), 256>>>(x);
    grn_finalize_kernel<<<BATCH, 32>>>();
    grn_apply_split_kernel<<<ROWS*DIM/4/256, 256>>>(x, gamma1, beta1, h1h, h1l);

    // QKV GEMM -> bf16 hi/lo qkv
    hmma_gemm_kernel<0,0,0,0,1><<<dim3(QKVN/HG_NT, ROWS/HG_MT), 256, HG_SMEM>>>(
        h1h, h1l, wqh, wql, nullptr, nullptr, nullptr, qvh, qvl, ROWS, QKVN, DIM);

    lam_kernel<<<1, 32>>>(lq1, lk1, lq2, lk2);

    // differential attention (HMMA) -> attn (bf16 split)
    diff_attn_mma_kernel<<<dim3(SEQ/AT_BQ, NH, BATCH), 256, AT_SMEM>>>(qvh, qvl, ath, atl);

    // proj + bias + residual(x) -> x2 (fp32)
    hmma_gemm_kernel<1,1,0,1,0><<<dim3(DIM/HG_NT, ROWS/HG_MT), 256, HG_SMEM>>>(
        ath, atl, wph, wpl, b_proj, x, x2p, nullptr, nullptr, ROWS, DIM, DIM);

    // GRN2 -> h2 (bf16 split)
    reduce_sq_kernel<<<dim3(64, BATCH), 256>>>(x2p);
    grn_finalize_kernel<<<BATCH, 32>>>();
    grn_apply_split_kernel<<<ROWS*DIM/4/256, 256>>>(x2p, gamma2, beta2, h2h, h2l);

    // FFN1: silu(h2@w1+b1) -> ffn1 (bf16 split only)
    hmma_gemm_kernel<1,0,1,0,1><<<dim3(MLP/HG_NT, ROWS/HG_MT), 256, HG_SMEM>>>(
        h2h, h2l, w1h, w1l, b1, nullptr, nullptr, f1h, f1l, ROWS, MLP, DIM);

    // FFN2: ffn1@w2 + b2 + x2 -> out (fp32)
    hmma_gemm_kernel<1,1,0,1,0><<<dim3(DIM/HG_NT, ROWS/HG_MT), 256, HG_SMEM>>>(
        f1h, f1l, w2h, w2l, b2, x2p, out, nullptr, nullptr, ROWS, DIM, MLP);
}